// round 1
// baseline (speedup 1.0000x reference)
#include <cuda_runtime.h>

// ---------------------------------------------------------------------------
// Quantum-head constants: the post-encoding circuit (RY layers + CZ) is a
// fixed REAL 4x4 matrix M. Only rows 0 and 3 are needed since
// <Z0>+<Z1> = 2*(p00 - p11). Computed once per launch from theta.
// ---------------------------------------------------------------------------
struct QC { float r0[4]; float r3[4]; };
__device__ QC g_qc;

__global__ void qsetup_kernel(const float* __restrict__ theta) {
    if (threadIdx.x != 0) return;
    float M[4][4];
#pragma unroll
    for (int i = 0; i < 4; i++)
#pragma unroll
        for (int j = 0; j < 4; j++) M[i][j] = (i == j) ? 1.0f : 0.0f;

#pragma unroll
    for (int d = 0; d < 2; d++) {          // Q_DEPTH = 2
        float a0 = theta[2 * d + 0] * 0.5f;
        float a1 = theta[2 * d + 1] * 0.5f;
        float c0 = cosf(a0), s0 = sinf(a0);
        float c1 = cosf(a1), s1 = sinf(a1);
        // RY(theta[d,0]) on qubit 0: mixes row pairs (0,1) and (2,3)
#pragma unroll
        for (int q1 = 0; q1 < 2; q1++)
#pragma unroll
            for (int j = 0; j < 4; j++) {
                float r0 = M[2 * q1 + 0][j], r1 = M[2 * q1 + 1][j];
                M[2 * q1 + 0][j] = c0 * r0 - s0 * r1;
                M[2 * q1 + 1][j] = s0 * r0 + c0 * r1;
            }
        // RY(theta[d,1]) on qubit 1: mixes row pairs (0,2) and (1,3)
#pragma unroll
        for (int q0 = 0; q0 < 2; q0++)
#pragma unroll
            for (int j = 0; j < 4; j++) {
                float r0 = M[q0][j], r1 = M[2 + q0][j];
                M[q0][j]     = c1 * r0 - s1 * r1;
                M[2 + q0][j] = s1 * r0 + c1 * r1;
            }
        // CZ: negate row 3 (|11>)
#pragma unroll
        for (int j = 0; j < 4; j++) M[3][j] = -M[3][j];
    }
#pragma unroll
    for (int j = 0; j < 4; j++) { g_qc.r0[j] = M[0][j]; g_qc.r3[j] = M[3][j]; }
}

// Accurate-enough fast tanh: 2 MUFU ops (EX2 + RCP), rel err ~1e-6.
__device__ __forceinline__ float fast_tanh(float x) {
    float ax = fabsf(x);
    float e  = __expf(-2.0f * ax);                 // MUFU.EX2 path, always in (0,1]
    float t  = __fdividef(1.0f - e, 1.0f + e);     // MUFU.RCP + mul
    return copysignf(t, x);
}

__device__ __forceinline__ float quantum_head(
    float x0, float x1,
    float m00, float m01, float m02, float m03,
    float m30, float m31, float m32, float m33)
{
    float s0, c0, s1, c1;
    __sincosf(x0 * 0.5f, &s0, &c0);
    __sincosf(x1 * 0.5f, &s1, &c1);
    // psi_enc = (c1c0, -i*c1s0, -i*s1c0, -s1s0); M is real so re/im never mix.
    float u = c1 * c0, v = s1 * s0, pp = c1 * s0, qq = s1 * c0;
    float r0 = fmaf(m00, u, -m03 * v);
    float i0 = fmaf(m01, pp,  m02 * qq);   // overall sign irrelevant (squared)
    float r3 = fmaf(m30, u, -m33 * v);
    float i3 = fmaf(m31, pp,  m32 * qq);
    float p0 = fmaf(r0, r0, i0 * i0);
    float p3 = fmaf(r3, r3, i3 * i3);
    return 2.0f * (p0 - p3);
}

__global__ __launch_bounds__(256)
void fused_kernel(const float4* __restrict__ x,
                  const float* __restrict__ Ws,  const float* __restrict__ bs,
                  const float* __restrict__ scales, const float* __restrict__ shifts,
                  const float* __restrict__ Wf,  const float* __restrict__ bf,
                  float2* __restrict__ out, int npairs)
{
    int i = blockIdx.x * blockDim.x + threadIdx.x;
    if (i >= npairs) return;

    float4 xv = __ldg(&x[i]);                 // two samples: (x,y) and (z,w)

    // ---------------- classical backbone (both samples share param regs) ----
    float ha0 = xv.x, ha1 = xv.y;
    float hb0 = xv.z, hb1 = xv.w;
#pragma unroll
    for (int l = 0; l < 5; l++) {
        float w00 = Ws[4 * l + 0], w01 = Ws[4 * l + 1];
        float w10 = Ws[4 * l + 2], w11 = Ws[4 * l + 3];
        float b0  = bs[2 * l + 0], b1  = bs[2 * l + 1];
        float sc0 = scales[2 * l + 0], sc1 = scales[2 * l + 1];
        float sh0 = shifts[2 * l + 0], sh1 = shifts[2 * l + 1];

        float ta0 = fast_tanh(fmaf(w00, ha0, fmaf(w01, ha1, b0)));
        float ta1 = fast_tanh(fmaf(w10, ha0, fmaf(w11, ha1, b1)));
        float tb0 = fast_tanh(fmaf(w00, hb0, fmaf(w01, hb1, b0)));
        float tb1 = fast_tanh(fmaf(w10, hb0, fmaf(w11, hb1, b1)));

        ha0 = fmaf(ta0, sc0, sh0);  ha1 = fmaf(ta1, sc1, sh1);
        hb0 = fmaf(tb0, sc0, sh0);  hb1 = fmaf(tb1, sc1, sh1);
    }
    float wf0 = Wf[0], wf1 = Wf[1], bff = bf[0];
    float ca = fmaf(wf0, ha0, fmaf(wf1, ha1, bff));
    float cb = fmaf(wf0, hb0, fmaf(wf1, hb1, bff));

    // ---------------- quantum head on the raw inputs ------------------------
    float m00 = g_qc.r0[0], m01 = g_qc.r0[1], m02 = g_qc.r0[2], m03 = g_qc.r0[3];
    float m30 = g_qc.r3[0], m31 = g_qc.r3[1], m32 = g_qc.r3[2], m33 = g_qc.r3[3];

    float qa = quantum_head(xv.x, xv.y, m00, m01, m02, m03, m30, m31, m32, m33);
    float qb = quantum_head(xv.z, xv.w, m00, m01, m02, m03, m30, m31, m32, m33);

    out[i] = make_float2(ca + qa, cb + qb);
}

extern "C" void kernel_launch(void* const* d_in, const int* in_sizes, int n_in,
                              void* d_out, int out_size)
{
    const float* x      = (const float*)d_in[0];   // [N, 2]
    const float* Ws     = (const float*)d_in[1];   // [5, 2, 2]
    const float* bs     = (const float*)d_in[2];   // [5, 2]
    const float* scales = (const float*)d_in[3];   // [5, 2]
    const float* shifts = (const float*)d_in[4];   // [5, 2]
    const float* Wf     = (const float*)d_in[5];   // [1, 2]
    const float* bf     = (const float*)d_in[6];   // [1]
    const float* theta  = (const float*)d_in[7];   // [2, 2]

    int n = out_size;            // number of samples (N = 4,194,304, even)
    int npairs = n >> 1;

    qsetup_kernel<<<1, 32>>>(theta);

    const int threads = 256;
    int blocks = (npairs + threads - 1) / threads;
    fused_kernel<<<blocks, threads>>>((const float4*)x, Ws, bs, scales, shifts,
                                      Wf, bf, (float2*)d_out, npairs);
}

// round 3
// speedup vs baseline: 1.7421x; 1.7421x over previous
#include <cuda_runtime.h>

// ---------------------------------------------------------------------------
// Packed parameters, produced once per launch by setup_kernel:
//  f[0..4] : fused layer weights W'_l = W_l * scale_{l-1}  (layer0 unfused)
//  f[5]    : (b'0_0, b'0_1, b'1_0, b'1_1)
//  f[6]    : (b'2_0, b'2_1, b'3_0, b'3_1)
//  f[7]    : (b'4_0, b'4_1, wf'0, wf'1)
//  f[8]    : (bf', K0, K1, K2)
//  f[9]    : (K3, K4, 0, 0)
// Quantum head collapses to q = K0 + K1 cx0 + K2 cx1 + K3 cx0cx1 + K4 sx0sx1
// (post-encoding circuit is a fixed REAL 4x4 matrix; only rows 0,3 matter
//  since <Z0>+<Z1> = 2(p00 - p11)).
// ---------------------------------------------------------------------------
__device__ float4 g_p[10];

__global__ void setup_kernel(const float* __restrict__ Ws,
                             const float* __restrict__ bs,
                             const float* __restrict__ scales,
                             const float* __restrict__ shifts,
                             const float* __restrict__ Wf,
                             const float* __restrict__ bf,
                             const float* __restrict__ theta)
{
    if (threadIdx.x != 0) return;

    // ---- fused backbone params --------------------------------------------
    float W[5][2][2], B[5][2];
#pragma unroll
    for (int l = 0; l < 5; l++) {
        float s0 = (l == 0) ? 1.0f : scales[2 * (l - 1) + 0];
        float s1 = (l == 0) ? 1.0f : scales[2 * (l - 1) + 1];
        float h0 = (l == 0) ? 0.0f : shifts[2 * (l - 1) + 0];
        float h1 = (l == 0) ? 0.0f : shifts[2 * (l - 1) + 1];
#pragma unroll
        for (int i = 0; i < 2; i++) {
            float w0 = Ws[4 * l + 2 * i + 0];
            float w1 = Ws[4 * l + 2 * i + 1];
            W[l][i][0] = w0 * s0;
            W[l][i][1] = w1 * s1;
            B[l][i] = w0 * h0 + w1 * h1 + bs[2 * l + i];
        }
    }
    float wf0 = Wf[0] * scales[8], wf1 = Wf[1] * scales[9];
    float bff = Wf[0] * shifts[8] + Wf[1] * shifts[9] + bf[0];

    // ---- quantum circuit matrix (RY layers + CZ, all real) ----------------
    float M[4][4];
#pragma unroll
    for (int i = 0; i < 4; i++)
#pragma unroll
        for (int j = 0; j < 4; j++) M[i][j] = (i == j) ? 1.0f : 0.0f;
#pragma unroll
    for (int d = 0; d < 2; d++) {                 // Q_DEPTH = 2
        float a0 = theta[2 * d + 0] * 0.5f;
        float a1 = theta[2 * d + 1] * 0.5f;
        float c0 = cosf(a0), s0 = sinf(a0);
        float c1 = cosf(a1), s1 = sinf(a1);
#pragma unroll
        for (int q1 = 0; q1 < 2; q1++)            // RY on qubit 0
#pragma unroll
            for (int j = 0; j < 4; j++) {
                float r0 = M[2 * q1 + 0][j], r1 = M[2 * q1 + 1][j];
                M[2 * q1 + 0][j] = c0 * r0 - s0 * r1;
                M[2 * q1 + 1][j] = s0 * r0 + c0 * r1;
            }
#pragma unroll
        for (int q0 = 0; q0 < 2; q0++)            // RY on qubit 1
#pragma unroll
            for (int j = 0; j < 4; j++) {
                float r0 = M[q0][j], r1 = M[2 + q0][j];
                M[q0][j]     = c1 * r0 - s1 * r1;
                M[2 + q0][j] = s1 * r0 + c1 * r1;
            }
#pragma unroll
        for (int j = 0; j < 4; j++) M[3][j] = -M[3][j];  // CZ
    }

    // ---- expand q(x0,x1) = K0 + K1 cx0 + K2 cx1 + K3 cx0cx1 + K4 sx0sx1 ---
    // per row i: a=mi0^2 b=mi3^2 c=mi1^2 d=mi2^2 e=mi1*mi2 - mi0*mi3
    float K[5];
    {
        float a0 = M[0][0] * M[0][0], b0 = M[0][3] * M[0][3];
        float c0 = M[0][1] * M[0][1], d0 = M[0][2] * M[0][2];
        float e0 = M[0][1] * M[0][2] - M[0][0] * M[0][3];
        float a3 = M[3][0] * M[3][0], b3 = M[3][3] * M[3][3];
        float c3 = M[3][1] * M[3][1], d3 = M[3][2] * M[3][2];
        float e3 = M[3][1] * M[3][2] - M[3][0] * M[3][3];
        K[0] = 0.5f * ((a0 + b0 + c0 + d0) - (a3 + b3 + c3 + d3));
        K[1] = 0.5f * ((a0 - b0 - c0 + d0) - (a3 - b3 - c3 + d3));
        K[2] = 0.5f * ((a0 - b0 + c0 - d0) - (a3 - b3 + c3 - d3));
        K[3] = 0.5f * ((a0 + b0 - c0 - d0) - (a3 + b3 - c3 - d3));
        K[4] = e0 - e3;
    }

    // ---- pack --------------------------------------------------------------
#pragma unroll
    for (int l = 0; l < 5; l++)
        g_p[l] = make_float4(W[l][0][0], W[l][0][1], W[l][1][0], W[l][1][1]);
    g_p[5] = make_float4(B[0][0], B[0][1], B[1][0], B[1][1]);
    g_p[6] = make_float4(B[2][0], B[2][1], B[3][0], B[3][1]);
    g_p[7] = make_float4(B[4][0], B[4][1], wf0, wf1);
    g_p[8] = make_float4(bff, K[0], K[1], K[2]);
    g_p[9] = make_float4(K[3], K[4], 0.0f, 0.0f);
}

// Hardware tanh: single MUFU.TANH, abs err ~1e-4 (net output err ~1e-4, OK).
__device__ __forceinline__ float htanh(float x) {
    float y;
    asm("tanh.approx.f32 %0, %1;" : "=f"(y) : "f"(x));
    return y;
}

__global__ __launch_bounds__(256)
void fused_kernel(const float4* __restrict__ x, float2* __restrict__ out,
                  int npairs)
{
    int i = blockIdx.x * blockDim.x + threadIdx.x;
    if (i >= npairs) return;

    float4 P0 = __ldg(&g_p[0]), P1 = __ldg(&g_p[1]), P2 = __ldg(&g_p[2]);
    float4 P3 = __ldg(&g_p[3]), P4 = __ldg(&g_p[4]), P5 = __ldg(&g_p[5]);
    float4 P6 = __ldg(&g_p[6]), P7 = __ldg(&g_p[7]), P8 = __ldg(&g_p[8]);
    float4 P9 = __ldg(&g_p[9]);

    float4 xv = __ldg(&x[i]);                 // two samples: (x,y) and (z,w)

    float ha0 = xv.x, ha1 = xv.y;
    float hb0 = xv.z, hb1 = xv.w;

#define LAYER(W, B0, B1)                                                \
    {                                                                   \
        float pa0 = fmaf((W).x, ha0, fmaf((W).y, ha1, (B0)));           \
        float pa1 = fmaf((W).z, ha0, fmaf((W).w, ha1, (B1)));           \
        float pb0 = fmaf((W).x, hb0, fmaf((W).y, hb1, (B0)));           \
        float pb1 = fmaf((W).z, hb0, fmaf((W).w, hb1, (B1)));           \
        ha0 = htanh(pa0); ha1 = htanh(pa1);                             \
        hb0 = htanh(pb0); hb1 = htanh(pb1);                             \
    }

    LAYER(P0, P5.x, P5.y)
    LAYER(P1, P5.z, P5.w)
    LAYER(P2, P6.x, P6.y)
    LAYER(P3, P6.z, P6.w)
    LAYER(P4, P7.x, P7.y)
#undef LAYER

    float ca = fmaf(P7.z, ha0, fmaf(P7.w, ha1, P8.x));
    float cb = fmaf(P7.z, hb0, fmaf(P7.w, hb1, P8.x));

    // quantum head: q = K0 + K1 cx0 + K2 cx1 + K3 cx0cx1 + K4 sx0sx1
    float sa0, ca0, sa1, ca1, sb0, cb0, sb1, cb1;
    __sincosf(xv.x, &sa0, &ca0);
    __sincosf(xv.y, &sa1, &ca1);
    __sincosf(xv.z, &sb0, &cb0);
    __sincosf(xv.w, &sb1, &cb1);

    float qa = fmaf(P8.z, ca0, P8.y);
    qa = fmaf(P8.w, ca1, qa);
    qa = fmaf(P9.x, ca0 * ca1, qa);
    qa = fmaf(P9.y, sa0 * sa1, qa);

    float qb = fmaf(P8.z, cb0, P8.y);
    qb = fmaf(P8.w, cb1, qb);
    qb = fmaf(P9.x, cb0 * cb1, qb);
    qb = fmaf(P9.y, sb0 * sb1, qb);

    out[i] = make_float2(ca + qa, cb + qb);
}

extern "C" void kernel_launch(void* const* d_in, const int* in_sizes, int n_in,
                              void* d_out, int out_size)
{
    const float* x      = (const float*)d_in[0];   // [N, 2]
    const float* Ws     = (const float*)d_in[1];   // [5, 2, 2]
    const float* bs     = (const float*)d_in[2];   // [5, 2]
    const float* scales = (const float*)d_in[3];   // [5, 2]
    const float* shifts = (const float*)d_in[4];   // [5, 2]
    const float* Wf     = (const float*)d_in[5];   // [1, 2]
    const float* bf     = (const float*)d_in[6];   // [1]
    const float* theta  = (const float*)d_in[7];   // [2, 2]

    int n = out_size;                 // N samples (even)
    int npairs = n >> 1;

    setup_kernel<<<1, 32>>>(Ws, bs, scales, shifts, Wf, bf, theta);

    const int threads = 256;
    int blocks = (npairs + threads - 1) / threads;
    fused_kernel<<<blocks, threads>>>((const float4*)x, (float2*)d_out, npairs);
}